// round 16
// baseline (speedup 1.0000x reference)
#include <cuda_runtime.h>
#include <cuda_fp16.h>
#include <cstdint>

#define H   2048
#define ISZ 4096
#define NE  8
#define T   2048

// ---------------- fp16 operand scratch ----------------------------------------
__device__ __half g_wg[8UL * 2048 * 8192];    // gup fp16 (layout preserved [k][n])
__device__ __half g_wd[8UL * 4096 * 2048];    // down fp16
__device__ __half g_sg16[2048UL * 4096];
__device__ __half g_su16[2048UL * 4096];
__device__ __half g_sd16[4096UL * 2048];
__device__ __half g_x16[2048UL * 2048];
__device__ __half g_act16[4096UL * 4096];     // rows 0..2047 shared, 2048..4095 routed
__device__ float g_scale[T];
__device__ float g_scale_perm[T];
__device__ int   g_eid[T];
__device__ int   g_perm[T];
__device__ int   g_off[NE + 1];

#define MMA_F16(d, a, b)                                                       \
    asm volatile("mma.sync.aligned.m16n8k16.row.col.f32.f16.f16.f32 "          \
                 "{%0,%1,%2,%3},{%4,%5,%6,%7},{%8,%9},{%0,%1,%2,%3};"          \
                 : "+f"(d[0]), "+f"(d[1]), "+f"(d[2]), "+f"(d[3])              \
                 : "r"(a[0]), "r"(a[1]), "r"(a[2]), "r"(a[3]),                 \
                   "r"(b[0]), "r"(b[1]))

__device__ __forceinline__ void ldsm_x4(uint32_t* r, uint32_t addr) {
    asm volatile("ldmatrix.sync.aligned.m8n8.x4.shared.b16 {%0,%1,%2,%3}, [%4];"
                 : "=r"(r[0]), "=r"(r[1]), "=r"(r[2]), "=r"(r[3]) : "r"(addr));
}
__device__ __forceinline__ void ldsm_x4t(uint32_t* r, uint32_t addr) {
    asm volatile("ldmatrix.sync.aligned.m8n8.x4.trans.shared.b16 {%0,%1,%2,%3}, [%4];"
                 : "=r"(r[0]), "=r"(r[1]), "=r"(r[2]), "=r"(r[3]) : "r"(addr));
}
__device__ __forceinline__ void cp16(uint32_t s, const void* g) {
    asm volatile("cp.async.cg.shared.global [%0], [%1], 16;\n" :: "r"(s), "l"(g));
}
__device__ __forceinline__ void cp_commit() { asm volatile("cp.async.commit_group;\n"); }
__device__ __forceinline__ void cp_wait2()  { asm volatile("cp.async.wait_group 2;\n"); }

__device__ __forceinline__ uint4 hpack8(const float4& v0, const float4& v1) {
    __half2 h0 = __floats2half2_rn(v0.x, v0.y);
    __half2 h1 = __floats2half2_rn(v0.z, v0.w);
    __half2 h2 = __floats2half2_rn(v1.x, v1.y);
    __half2 h3 = __floats2half2_rn(v1.z, v1.w);
    return make_uint4(*(uint32_t*)&h0, *(uint32_t*)&h1, *(uint32_t*)&h2, *(uint32_t*)&h3);
}

// ---------------- fp32 -> fp16 convert (layout preserved) ---------------------
__global__ void hconv_kernel(const float4* __restrict__ src, uint4* __restrict__ dst, long n16) {
    const long stride = (long)gridDim.x * blockDim.x;
    for (long i = (long)blockIdx.x * blockDim.x + threadIdx.x; i < n16; i += stride)
        dst[i] = hpack8(src[2 * i], src[2 * i + 1]);
}

__global__ void zero_kernel(float4* __restrict__ p, int n4) {
    const int stride = gridDim.x * blockDim.x;
    for (int i = blockIdx.x * blockDim.x + threadIdx.x; i < n4; i += stride)
        p[i] = make_float4(0.f, 0.f, 0.f, 0.f);
}

// ---------------- router ------------------------------------------------------
__global__ void router_kernel(const float* __restrict__ x, const float* __restrict__ rw) {
    const int t = blockIdx.x;
    const int tid = threadIdx.x;
    float acc[NE];
#pragma unroll
    for (int e = 0; e < NE; e++) acc[e] = 0.f;
    const float* xr = x + (size_t)t * H;
    for (int h = tid; h < H; h += 256) {
        float xv = xr[h];
#pragma unroll
        for (int e = 0; e < NE; e++) acc[e] += xv * rw[e * H + h];
    }
#pragma unroll
    for (int e = 0; e < NE; e++)
#pragma unroll
        for (int o = 16; o > 0; o >>= 1) acc[e] += __shfl_xor_sync(0xffffffffu, acc[e], o);
    __shared__ float red[NE][8];
    if ((tid & 31) == 0) {
#pragma unroll
        for (int e = 0; e < NE; e++) red[e][tid >> 5] = acc[e];
    }
    __syncthreads();
    if (tid == 0) {
        float best = -1e30f; int be = 0;
#pragma unroll
        for (int e = 0; e < NE; e++) {
            float v = 0.f;
#pragma unroll
            for (int w = 0; w < 8; w++) v += red[e][w];
            if (v > best) { best = v; be = e; }
        }
        g_scale[t] = 1.f / (1.f + expf(-best));
        g_eid[t] = be;
    }
}

// ---------------- bucket ------------------------------------------------------
__global__ void bucket_kernel() {
    __shared__ int cnt[NE], cur[NE];
    const int tid = threadIdx.x;
    if (tid < NE) cnt[tid] = 0;
    __syncthreads();
    for (int t = tid; t < T; t += 256) atomicAdd(&cnt[g_eid[t]], 1);
    __syncthreads();
    if (tid == 0) {
        int a = 0;
        for (int e = 0; e < NE; e++) { g_off[e] = a; cur[e] = a; a += cnt[e]; }
        g_off[NE] = a;
    }
    __syncthreads();
    for (int t = tid; t < T; t += 256) {
        int e = g_eid[t];
        int p = atomicAdd(&cur[e], 1);
        g_perm[p] = t;
        g_scale_perm[p] = g_scale[t];
    }
}

// SMEM: 4 stages x (A 128rows x 80B + B 32k x 272B) = 4 x 18944 = 75776
#define AST   10240
#define STG   18944
#define SMEM_SZ (4 * STG)

// ---------------- GEMM1: x16[M,2048] x (gate|up)[2048, 64+64] + SwiGLU --------
// CTA 128m x (64g+64u), 4 warps (2m x 2n), warp 64m x (32g+32u). mi=4. BK=32.
__global__ __launch_bounds__(128) void gemm1_kernel() {
    extern __shared__ __align__(16) char smem[];
    const uint32_t sb = (uint32_t)__cvta_generic_to_shared(smem);

    const int mTile = blockIdx.x, nTile = blockIdx.y, e = blockIdx.z;
    int M, offE, actBase;
    size_t ldb;
    const __half *pg, *pu;
    if (e < NE) {
        offE = g_off[e]; M = g_off[e + 1] - offE;
        if (mTile * 128 >= M) return;
        pg = g_wg + (size_t)e * H * (2 * ISZ) + nTile * 64;
        pu = pg + ISZ; ldb = 2 * ISZ; actBase = T + offE;
    } else {
        offE = 0; M = T;
        pg = g_sg16 + nTile * 64; pu = g_su16 + nTile * 64; ldb = ISZ; actBase = 0;
    }
    const int tid = threadIdx.x, lane = tid & 31, warp = tid >> 5;
    const int wm = warp & 1, wn = warp >> 1;

    // A loader: each thread owns row tid, 4 chunks of 16B
    const int arow = tid;
    const int lr = mTile * 128 + arow;
    const int ri = (e < NE) ? g_perm[offE + min(lr, M - 1)] : lr;
    const __half* aptr = g_x16 + (size_t)ri * H;
    const uint32_t awA = arow * 80;

    // B loader: bkr = tid>>2 (0..31), bc = tid&3; 2 gate chunks + 2 up chunks
    const int bkr = tid >> 2, bc = tid & 3;
    const __half* pgt = pg + (size_t)bkr * ldb + bc * 16;
    const __half* put = pu + (size_t)bkr * ldb + bc * 16;
    const uint32_t bwG = bkr * 272 + bc * 32;
    const uint32_t bwU = bwG + 128;

    // fragment offsets
    const int tq = lane >> 3, tr = lane & 7;
    uint32_t offA[4];
#pragma unroll
    for (int mi = 0; mi < 4; mi++) {
        int row = wm * 64 + mi * 16 + (tq & 1) * 8 + tr;
        offA[mi] = (uint32_t)(row * 80 + (tq >> 1) * 16);
    }
    const int kB = (tq & 1) * 8 + tr, ngB = tq >> 1;
    uint32_t offB[2][2];
#pragma unroll
    for (int hh = 0; hh < 2; hh++)
#pragma unroll
        for (int g = 0; g < 2; g++)
            offB[hh][g] = (uint32_t)(kB * 272 + hh * 128 + (wn * 32 + g * 16 + ngB * 8) * 2);

    float acc[2][4][4][4];
#pragma unroll
    for (int h = 0; h < 2; h++)
#pragma unroll
        for (int mi = 0; mi < 4; mi++)
#pragma unroll
            for (int ni = 0; ni < 4; ni++)
#pragma unroll
                for (int r = 0; r < 4; r++) acc[h][mi][ni][r] = 0.f;

#define G1_FILL(s, k0)                                                          \
    {                                                                           \
        const uint32_t stg = sb + (s) * STG;                                    \
        _Pragma("unroll")                                                       \
        for (int aq = 0; aq < 4; aq++)                                          \
            cp16(stg + awA + aq * 16, aptr + (k0) + aq * 8);                    \
        const size_t ko = (size_t)(k0) * ldb;                                   \
        _Pragma("unroll")                                                       \
        for (int j = 0; j < 2; j++) {                                           \
            cp16(stg + AST + bwG + j * 16, pgt + ko + j * 8);                   \
            cp16(stg + AST + bwU + j * 16, put + ko + j * 8);                   \
        }                                                                       \
    }

    const int KT = H / 32;
    G1_FILL(0, 0)  cp_commit();
    G1_FILL(1, 32) cp_commit();
    G1_FILL(2, 64) cp_commit();

    for (int c = 0; c < KT; ++c) {
        const int s = c & 3;
        cp_wait2();
        __syncthreads();
        if (c + 3 < KT) { G1_FILL((c + 3) & 3, (c + 3) * 32) }
        cp_commit();

        const uint32_t aS = sb + s * STG;
        const uint32_t bS = aS + AST;
#pragma unroll
        for (int ks = 0; ks < 2; ++ks) {
            uint32_t af[4][4];
#pragma unroll
            for (int mi = 0; mi < 4; mi++)
                ldsm_x4(af[mi], aS + offA[mi] + ks * 32);
#pragma unroll
            for (int hh = 0; hh < 2; ++hh) {
#pragma unroll
                for (int g = 0; g < 2; ++g) {
                    uint32_t b4[4];
                    ldsm_x4t(b4, bS + offB[hh][g] + ks * 16 * 272);
#pragma unroll
                    for (int sub = 0; sub < 2; ++sub) {
                        const int ni = 2 * g + sub;
                        uint32_t bf[2] = { b4[sub * 2], b4[sub * 2 + 1] };
#pragma unroll
                        for (int mi = 0; mi < 4; ++mi)
                            MMA_F16(acc[hh][mi][ni], af[mi], bf);
                    }
                }
            }
        }
    }

    // epilogue: act = (s*up) * silu(s*gate) -> fp16
#pragma unroll
    for (int mi = 0; mi < 4; ++mi) {
        const int r0 = mTile * 128 + wm * 64 + mi * 16 + (lane >> 2);
        const int r1 = r0 + 8;
        const bool v0 = r0 < M, v1 = r1 < M;
        float s0 = 1.f, s1 = 1.f;
        if (e < NE) {
            s0 = v0 ? g_scale_perm[offE + r0] : 0.f;
            s1 = v1 ? g_scale_perm[offE + r1] : 0.f;
        }
#pragma unroll
        for (int ni = 0; ni < 4; ++ni) {
            const int col = nTile * 64 + wn * 32 + ni * 8 + (lane & 3) * 2;
            if (v0) {
                float gA = s0 * acc[0][mi][ni][0], gB = s0 * acc[0][mi][ni][1];
                float uA = s0 * acc[1][mi][ni][0], uB = s0 * acc[1][mi][ni][1];
                __half2 h = __floats2half2_rn(uA * (gA / (1.f + expf(-gA))),
                                              uB * (gB / (1.f + expf(-gB))));
                *(uint32_t*)&g_act16[(size_t)(actBase + r0) * ISZ + col] = *(uint32_t*)&h;
            }
            if (v1) {
                float gA = s1 * acc[0][mi][ni][2], gB = s1 * acc[0][mi][ni][3];
                float uA = s1 * acc[1][mi][ni][2], uB = s1 * acc[1][mi][ni][3];
                __half2 h = __floats2half2_rn(uA * (gA / (1.f + expf(-gA))),
                                              uB * (gB / (1.f + expf(-gB))));
                *(uint32_t*)&g_act16[(size_t)(actBase + r1) * ISZ + col] = *(uint32_t*)&h;
            }
        }
    }
}

// ---------------- GEMM2 (merged): act16[M,4096] x down16[4096,2048] -----------
// CTA 128m x 128n, 4 warps (2m x 2n), warp 64x64, mi=4, ni=8. BK=32.
// z = 0..7 routed experts, z = 8 shared. atomicAdd epilogue onto zeroed out.
__global__ __launch_bounds__(128) void gemm2_kernel(float* __restrict__ out) {
    extern __shared__ __align__(16) char smem[];
    const uint32_t sb = (uint32_t)__cvta_generic_to_shared(smem);

    const int mTile = blockIdx.x, nTile = blockIdx.y, z = blockIdx.z;
    const int routed = (z < NE);
    int M, offE, actBase;
    const __half* Bd;
    if (routed) {
        offE = g_off[z]; M = g_off[z + 1] - offE;
        if (mTile * 128 >= M) return;
        actBase = T + offE;
        Bd = g_wd + (size_t)z * ISZ * H + nTile * 128;
    } else {
        offE = 0; M = T; actBase = 0;
        Bd = g_sd16 + nTile * 128;
    }
    const int tid = threadIdx.x, lane = tid & 31, warp = tid >> 5;
    const int wm = warp & 1, wn = warp >> 1;

    const int arow = tid;
    const int lr = mTile * 128 + arow;
    const __half* aptr = g_act16 + (size_t)(actBase + min(lr, M - 1)) * ISZ;
    const uint32_t awA = arow * 80;

    const int bkr = tid >> 2, bc = tid & 3;
    const __half* pbt = Bd + (size_t)bkr * H + bc * 32;
    const uint32_t bw0 = bkr * 272 + bc * 64;

    const int tq = lane >> 3, tr = lane & 7;
    uint32_t offA[4];
#pragma unroll
    for (int mi = 0; mi < 4; mi++) {
        int row = wm * 64 + mi * 16 + (tq & 1) * 8 + tr;
        offA[mi] = (uint32_t)(row * 80 + (tq >> 1) * 16);
    }
    const int kB = (tq & 1) * 8 + tr, ngB = tq >> 1;
    uint32_t offB[4];
#pragma unroll
    for (int g = 0; g < 4; g++)
        offB[g] = (uint32_t)(kB * 272 + (wn * 64 + g * 16 + ngB * 8) * 2);

    float acc[4][8][4];
#pragma unroll
    for (int mi = 0; mi < 4; mi++)
#pragma unroll
        for (int ni = 0; ni < 8; ni++)
#pragma unroll
            for (int r = 0; r < 4; r++) acc[mi][ni][r] = 0.f;

#define G2_FILL(s, k0)                                                          \
    {                                                                           \
        const uint32_t stg = sb + (s) * STG;                                    \
        _Pragma("unroll")                                                       \
        for (int aq = 0; aq < 4; aq++)                                          \
            cp16(stg + awA + aq * 16, aptr + (k0) + aq * 8);                    \
        const size_t ko = (size_t)(k0) * H;                                     \
        _Pragma("unroll")                                                       \
        for (int j = 0; j < 4; j++)                                             \
            cp16(stg + AST + bw0 + j * 16, pbt + ko + j * 8);                   \
    }

    const int KT = ISZ / 32;
    G2_FILL(0, 0)  cp_commit();
    G2_FILL(1, 32) cp_commit();
    G2_FILL(2, 64) cp_commit();

    for (int c = 0; c < KT; ++c) {
        const int s = c & 3;
        cp_wait2();
        __syncthreads();
        if (c + 3 < KT) { G2_FILL((c + 3) & 3, (c + 3) * 32) }
        cp_commit();

        const uint32_t aS = sb + s * STG;
        const uint32_t bS = aS + AST;
#pragma unroll
        for (int ks = 0; ks < 2; ++ks) {
            uint32_t af[4][4];
#pragma unroll
            for (int mi = 0; mi < 4; mi++)
                ldsm_x4(af[mi], aS + offA[mi] + ks * 32);
#pragma unroll
            for (int g = 0; g < 4; ++g) {
                uint32_t b4[4];
                ldsm_x4t(b4, bS + offB[g] + ks * 16 * 272);
#pragma unroll
                for (int sub = 0; sub < 2; ++sub) {
                    const int ni = 2 * g + sub;
                    uint32_t bf[2] = { b4[sub * 2], b4[sub * 2 + 1] };
#pragma unroll
                    for (int mi = 0; mi < 4; ++mi)
                        MMA_F16(acc[mi][ni], af[mi], bf);
                }
            }
        }
    }

#pragma unroll
    for (int mi = 0; mi < 4; ++mi) {
        const int r0 = mTile * 128 + wm * 64 + mi * 16 + (lane >> 2);
        const int r1 = r0 + 8;
        const bool v0 = r0 < M, v1 = r1 < M;
        int t0 = 0, t1 = 0;
        if (routed) {
            if (v0) t0 = g_perm[offE + r0];
            if (v1) t1 = g_perm[offE + r1];
        } else { t0 = r0; t1 = r1; }
#pragma unroll
        for (int ni = 0; ni < 8; ++ni) {
            const int col = nTile * 128 + wn * 64 + ni * 8 + (lane & 3) * 2;
            if (v0) {
                float* p = &out[(size_t)t0 * H + col];
                atomicAdd(p, acc[mi][ni][0]);
                atomicAdd(p + 1, acc[mi][ni][1]);
            }
            if (v1) {
                float* p = &out[(size_t)t1 * H + col];
                atomicAdd(p, acc[mi][ni][2]);
                atomicAdd(p + 1, acc[mi][ni][3]);
            }
        }
    }
}

// ---------------- launch ------------------------------------------------------
extern "C" void kernel_launch(void* const* d_in, const int* in_sizes, int n_in,
                              void* d_out, int out_size) {
    const float* x   = (const float*)d_in[0];
    const float* rw  = (const float*)d_in[1];
    const float* gup = (const float*)d_in[2];
    const float* dwn = (const float*)d_in[3];
    const float* sg  = (const float*)d_in[4];
    const float* su  = (const float*)d_in[5];
    const float* sd  = (const float*)d_in[6];
    float* out = (float*)d_out;

    cudaFuncSetAttribute(gemm1_kernel, cudaFuncAttributeMaxDynamicSharedMemorySize, SMEM_SZ);
    cudaFuncSetAttribute(gemm2_kernel, cudaFuncAttributeMaxDynamicSharedMemorySize, SMEM_SZ);

    void *wg, *wd, *sg16, *su16, *sd16, *x16;
    cudaGetSymbolAddress(&wg, g_wg);     cudaGetSymbolAddress(&wd, g_wd);
    cudaGetSymbolAddress(&sg16, g_sg16); cudaGetSymbolAddress(&su16, g_su16);
    cudaGetSymbolAddress(&sd16, g_sd16); cudaGetSymbolAddress(&x16, g_x16);

    // side stream: converts needed only by gemm2 (down, shared_down) overlap gemm1
    cudaStream_t s1;
    cudaStreamCreate(&s1);
    cudaEvent_t e0, e1;
    cudaEventCreateWithFlags(&e0, cudaEventDisableTiming);
    cudaEventCreateWithFlags(&e1, cudaEventDisableTiming);

    cudaEventRecord(e0, 0);
    cudaStreamWaitEvent(s1, e0, 0);
    hconv_kernel<<<8192, 256, 0, s1>>>((const float4*)dwn, (uint4*)wd, 8L * 4096 * 2048 / 8);
    hconv_kernel<<<2048, 256, 0, s1>>>((const float4*)sd,  (uint4*)sd16, 4096L * 2048 / 8);
    cudaEventRecord(e1, s1);

    router_kernel<<<T, 256>>>(x, rw);
    bucket_kernel<<<1, 256>>>();
    hconv_kernel<<<8192, 256>>>((const float4*)gup, (uint4*)wg,   8L * 2048 * 8192 / 8);
    hconv_kernel<<<2048, 256>>>((const float4*)sg,  (uint4*)sg16, 2048L * 4096 / 8);
    hconv_kernel<<<2048, 256>>>((const float4*)su,  (uint4*)su16, 2048L * 4096 / 8);
    hconv_kernel<<<1024, 256>>>((const float4*)x,   (uint4*)x16,  2048L * 2048 / 8);
    zero_kernel<<<1024, 256>>>((float4*)out, T * H / 4);

    gemm1_kernel<<<dim3(16, ISZ / 64, NE + 1), 128, SMEM_SZ>>>();

    cudaStreamWaitEvent(0, e1, 0);
    gemm2_kernel<<<dim3(16, H / 128, NE + 1), 128, SMEM_SZ>>>(out);

    cudaStreamDestroy(s1);
    cudaEventDestroy(e0);
    cudaEventDestroy(e1);
}